// round 1
// baseline (speedup 1.0000x reference)
#include <cuda_runtime.h>
#include <cuda_bf16.h>

#define N_NODES 100000
#define D_DIM   64
#define E_EDGES 1600000

// Scratch: per-node gate partials (no cudaMalloc allowed)
__device__ float g_adst[N_NODES];   // h[i] . w_dst + bias
__device__ float g_asrc[N_NODES];   // h[i] . w_src

// ---------------------------------------------------------------------------
// Kernel 1: one warp per node. Lane k handles columns 2k, 2k+1 (float2).
// Also zeroes the output buffer (2 floats per thread covers N*D exactly).
// ---------------------------------------------------------------------------
__global__ void node_dots_kernel(const float* __restrict__ h,
                                 const float* __restrict__ gate_w,
                                 const float* __restrict__ gate_b,
                                 float* __restrict__ out)
{
    int tid  = blockIdx.x * blockDim.x + threadIdx.x;
    int warp = tid >> 5;
    int lane = tid & 31;

    // zero output: thread t zeroes out[2t], out[2t+1]
    long long zi = (long long)tid * 2;
    if (zi + 1 < (long long)N_NODES * D_DIM) {
        *reinterpret_cast<float2*>(out + zi) = make_float2(0.f, 0.f);
    }

    if (warp >= N_NODES) return;

    float2 hv = *reinterpret_cast<const float2*>(h + (long long)warp * D_DIM + lane * 2);
    float2 wd = *reinterpret_cast<const float2*>(gate_w + lane * 2);
    float2 ws = *reinterpret_cast<const float2*>(gate_w + D_DIM + lane * 2);

    float pd = hv.x * wd.x + hv.y * wd.y;
    float ps = hv.x * ws.x + hv.y * ws.y;

    #pragma unroll
    for (int off = 16; off > 0; off >>= 1) {
        pd += __shfl_xor_sync(0xFFFFFFFFu, pd, off);
        ps += __shfl_xor_sync(0xFFFFFFFFu, ps, off);
    }

    if (lane == 0) {
        g_adst[warp] = pd + gate_b[0];  // fold bias in once
        g_asrc[warp] = ps;
    }
}

// ---------------------------------------------------------------------------
// Kernel 2: edge scatter. 16 lanes per edge (2 edges per warp).
// Lane sub-index hl in [0,16): handles float4 at column hl*4.
// Gate coefficient computed once per edge (lanes 0 and 16), shfl-broadcast.
// Accumulate into out[dst] with vector reduction red.global.add.v4.f32.
// ---------------------------------------------------------------------------
__global__ void edge_scatter_kernel(const float* __restrict__ h,
                                    const float* __restrict__ dnorm,
                                    const int*   __restrict__ src,
                                    const int*   __restrict__ dst,
                                    float* __restrict__ out)
{
    int t = blockIdx.x * blockDim.x + threadIdx.x;
    int e = t >> 4;
    if (e >= E_EDGES) return;

    int lane = threadIdx.x & 31;
    int hl   = lane & 15;

    int s = src[e];
    int d = dst[e];

    float coef = 0.f;
    if (hl == 0) {
        float g = tanhf(g_adst[d] + g_asrc[s]);
        coef = g * dnorm[d] * dnorm[s];
    }
    // broadcast from lane 0 (lower half-warp) / lane 16 (upper half-warp)
    coef = __shfl_sync(0xFFFFFFFFu, coef, lane & 16);

    float4 hv = *reinterpret_cast<const float4*>(h + (long long)s * D_DIM + hl * 4);

    float* p = out + (long long)d * D_DIM + hl * 4;
    asm volatile("red.global.add.v4.f32 [%0], {%1, %2, %3, %4};"
                 :: "l"(p),
                    "f"(hv.x * coef), "f"(hv.y * coef),
                    "f"(hv.z * coef), "f"(hv.w * coef)
                 : "memory");
}

// ---------------------------------------------------------------------------
// Launch
// ---------------------------------------------------------------------------
extern "C" void kernel_launch(void* const* d_in, const int* in_sizes, int n_in,
                              void* d_out, int out_size)
{
    const float* h      = (const float*)d_in[0];   // (N, 64)
    const float* dnorm  = (const float*)d_in[1];   // (N,)
    const float* gate_w = (const float*)d_in[2];   // (1, 128)
    const float* gate_b = (const float*)d_in[3];   // (1,)
    const int*   src    = (const int*)  d_in[4];   // (E,)
    const int*   dst    = (const int*)  d_in[5];   // (E,)
    float* out = (float*)d_out;                    // (N, 64) float32

    // Kernel 1: N_NODES warps -> 3.2M threads
    {
        int threads = 256;
        long long total = (long long)N_NODES * 32;
        int blocks = (int)((total + threads - 1) / threads);
        node_dots_kernel<<<blocks, threads>>>(h, gate_w, gate_b, out);
    }

    // Kernel 2: 16 threads per edge -> 25.6M threads
    {
        int threads = 256;
        long long total = (long long)E_EDGES * 16;
        int blocks = (int)((total + threads - 1) / threads);
        edge_scatter_kernel<<<blocks, threads>>>(h, dnorm, src, dst, out);
    }
}

// round 2
// speedup vs baseline: 1.0731x; 1.0731x over previous
#include <cuda_runtime.h>
#include <cuda_bf16.h>

#define N_NODES 100000
#define D_DIM   64
#define E_EDGES 1600000

#define SCAN_BLOCK 1024
#define N_SCAN_BLOCKS ((N_NODES + SCAN_BLOCK - 1) / SCAN_BLOCK)   // 98

// ---- device scratch (no cudaMalloc allowed) ----
__device__ float g_adst[N_NODES];          // h[i].w_dst + bias
__device__ float g_asrc[N_NODES];          // h[i].w_src
__device__ int   g_counts[N_NODES];        // in-degree histogram
__device__ int   g_offsets[N_NODES + 1];   // CSR row offsets
__device__ int   g_cursor[N_NODES];        // scatter cursors
__device__ int   g_blocksums[N_SCAN_BLOCKS];
__device__ int   g_blockbase[N_SCAN_BLOCKS];
__device__ int   g_edge_src[E_EDGES];      // CSR column (src node) list

// ---------------------------------------------------------------------------
// K1: per-node gate partials (warp per node) + zero the histogram
// ---------------------------------------------------------------------------
__global__ void node_dots_kernel(const float* __restrict__ h,
                                 const float* __restrict__ gate_w,
                                 const float* __restrict__ gate_b)
{
    int tid  = blockIdx.x * blockDim.x + threadIdx.x;
    int warp = tid >> 5;
    int lane = tid & 31;
    if (warp >= N_NODES) return;

    float2 hv = *reinterpret_cast<const float2*>(h + (long long)warp * D_DIM + lane * 2);
    float2 wd = *reinterpret_cast<const float2*>(gate_w + lane * 2);
    float2 ws = *reinterpret_cast<const float2*>(gate_w + D_DIM + lane * 2);

    float pd = hv.x * wd.x + hv.y * wd.y;
    float ps = hv.x * ws.x + hv.y * ws.y;

    #pragma unroll
    for (int off = 16; off > 0; off >>= 1) {
        pd += __shfl_xor_sync(0xFFFFFFFFu, pd, off);
        ps += __shfl_xor_sync(0xFFFFFFFFu, ps, off);
    }

    if (lane == 0) {
        g_adst[warp]   = pd + gate_b[0];
        g_asrc[warp]   = ps;
        g_counts[warp] = 0;
    }
}

// ---------------------------------------------------------------------------
// K2: in-degree histogram
// ---------------------------------------------------------------------------
__global__ void histogram_kernel(const int* __restrict__ dst)
{
    int stride = gridDim.x * blockDim.x;
    for (int e = blockIdx.x * blockDim.x + threadIdx.x; e < E_EDGES; e += stride)
        atomicAdd(&g_counts[dst[e]], 1);
}

// ---------------------------------------------------------------------------
// K3: per-block exclusive scan (Hillis-Steele in smem)
// ---------------------------------------------------------------------------
__global__ void scan_blocks_kernel()
{
    __shared__ int sdata[SCAN_BLOCK];
    int tid = threadIdx.x;
    int i   = blockIdx.x * SCAN_BLOCK + tid;
    int v   = (i < N_NODES) ? g_counts[i] : 0;
    sdata[tid] = v;
    __syncthreads();

    #pragma unroll
    for (int off = 1; off < SCAN_BLOCK; off <<= 1) {
        int t = (tid >= off) ? sdata[tid - off] : 0;
        __syncthreads();
        sdata[tid] += t;
        __syncthreads();
    }

    if (i < N_NODES) g_offsets[i] = sdata[tid] - v;       // exclusive, block-local
    if (tid == SCAN_BLOCK - 1) g_blocksums[blockIdx.x] = sdata[tid];
}

// ---------------------------------------------------------------------------
// K4: scan the block sums (single block)
// ---------------------------------------------------------------------------
__global__ void scan_sums_kernel()
{
    __shared__ int sdata[128];
    int tid = threadIdx.x;  // blockDim = 128 >= N_SCAN_BLOCKS
    int v = (tid < N_SCAN_BLOCKS) ? g_blocksums[tid] : 0;
    sdata[tid] = v;
    __syncthreads();

    #pragma unroll
    for (int off = 1; off < 128; off <<= 1) {
        int t = (tid >= off) ? sdata[tid - off] : 0;
        __syncthreads();
        sdata[tid] += t;
        __syncthreads();
    }

    if (tid < N_SCAN_BLOCKS) g_blockbase[tid] = sdata[tid] - v;  // exclusive
}

// ---------------------------------------------------------------------------
// K5: add block bases; init cursors; fix up offsets[N]
// ---------------------------------------------------------------------------
__global__ void add_base_kernel()
{
    int stride = gridDim.x * blockDim.x;
    for (int i = blockIdx.x * blockDim.x + threadIdx.x; i < N_NODES; i += stride) {
        int val = g_offsets[i] + g_blockbase[i / SCAN_BLOCK];
        g_offsets[i] = val;
        g_cursor[i]  = val;
    }
    if (blockIdx.x == 0 && threadIdx.x == 0) g_offsets[N_NODES] = E_EDGES;
}

// ---------------------------------------------------------------------------
// K6: scatter src ids into CSR
// ---------------------------------------------------------------------------
__global__ void csr_scatter_kernel(const int* __restrict__ src,
                                   const int* __restrict__ dst)
{
    int stride = gridDim.x * blockDim.x;
    for (int e = blockIdx.x * blockDim.x + threadIdx.x; e < E_EDGES; e += stride) {
        int pos = atomicAdd(&g_cursor[dst[e]], 1);
        g_edge_src[pos] = src[e];
    }
}

// ---------------------------------------------------------------------------
// K7: gather-accumulate. One warp per dst node, float2 per lane, no atomics.
// Coefs for up to 32 edges computed in parallel (one tanh per edge),
// then broadcast; h[src] rows streamed with 4-deep MLP.
// ---------------------------------------------------------------------------
__global__ void gather_kernel(const float* __restrict__ h,
                              const float* __restrict__ dnorm,
                              float* __restrict__ out)
{
    int tid  = blockIdx.x * blockDim.x + threadIdx.x;
    int d    = tid >> 5;
    int lane = tid & 31;
    if (d >= N_NODES) return;

    int beg = g_offsets[d];
    int end = g_offsets[d + 1];

    float adst_d = g_adst[d];
    float dnd    = dnorm[d];

    float accx = 0.f, accy = 0.f;

    for (int base = beg; base < end; base += 32) {
        int idx = base + lane;
        int s = 0;
        float coef = 0.f;
        if (idx < end) {
            s = g_edge_src[idx];
            coef = tanhf(adst_d + g_asrc[s]) * dnd * dnorm[s];
        }
        int cnt = end - base;
        if (cnt > 32) cnt = 32;

        int j = 0;
        for (; j + 4 <= cnt; j += 4) {
            int   s0 = __shfl_sync(0xFFFFFFFFu, s, j);
            int   s1 = __shfl_sync(0xFFFFFFFFu, s, j + 1);
            int   s2 = __shfl_sync(0xFFFFFFFFu, s, j + 2);
            int   s3 = __shfl_sync(0xFFFFFFFFu, s, j + 3);
            float c0 = __shfl_sync(0xFFFFFFFFu, coef, j);
            float c1 = __shfl_sync(0xFFFFFFFFu, coef, j + 1);
            float c2 = __shfl_sync(0xFFFFFFFFu, coef, j + 2);
            float c3 = __shfl_sync(0xFFFFFFFFu, coef, j + 3);
            float2 a0 = *reinterpret_cast<const float2*>(h + (long long)s0 * D_DIM + lane * 2);
            float2 a1 = *reinterpret_cast<const float2*>(h + (long long)s1 * D_DIM + lane * 2);
            float2 a2 = *reinterpret_cast<const float2*>(h + (long long)s2 * D_DIM + lane * 2);
            float2 a3 = *reinterpret_cast<const float2*>(h + (long long)s3 * D_DIM + lane * 2);
            accx = fmaf(c0, a0.x, accx); accy = fmaf(c0, a0.y, accy);
            accx = fmaf(c1, a1.x, accx); accy = fmaf(c1, a1.y, accy);
            accx = fmaf(c2, a2.x, accx); accy = fmaf(c2, a2.y, accy);
            accx = fmaf(c3, a3.x, accx); accy = fmaf(c3, a3.y, accy);
        }
        for (; j < cnt; j++) {
            int   sj = __shfl_sync(0xFFFFFFFFu, s, j);
            float cj = __shfl_sync(0xFFFFFFFFu, coef, j);
            float2 av = *reinterpret_cast<const float2*>(h + (long long)sj * D_DIM + lane * 2);
            accx = fmaf(cj, av.x, accx);
            accy = fmaf(cj, av.y, accy);
        }
    }

    *reinterpret_cast<float2*>(out + (long long)d * D_DIM + lane * 2) =
        make_float2(accx, accy);
}

// ---------------------------------------------------------------------------
// Launch
// ---------------------------------------------------------------------------
extern "C" void kernel_launch(void* const* d_in, const int* in_sizes, int n_in,
                              void* d_out, int out_size)
{
    const float* h      = (const float*)d_in[0];   // (N, 64)
    const float* dnorm  = (const float*)d_in[1];   // (N,)
    const float* gate_w = (const float*)d_in[2];   // (1, 128)
    const float* gate_b = (const float*)d_in[3];   // (1,)
    const int*   src    = (const int*)  d_in[4];   // (E,)
    const int*   dst    = (const int*)  d_in[5];   // (E,)
    float* out = (float*)d_out;                    // (N, 64) float32

    // K1: node dot products + zero histogram  (N warps)
    {
        long long total = (long long)N_NODES * 32;
        int blocks = (int)((total + 255) / 256);
        node_dots_kernel<<<blocks, 256>>>(h, gate_w, gate_b);
    }
    // K2: in-degree histogram
    histogram_kernel<<<2048, 256>>>(dst);
    // K3-K5: exclusive scan of counts -> offsets (+cursors)
    scan_blocks_kernel<<<N_SCAN_BLOCKS, SCAN_BLOCK>>>();
    scan_sums_kernel<<<1, 128>>>();
    add_base_kernel<<<256, 256>>>();
    // K6: CSR scatter
    csr_scatter_kernel<<<2048, 256>>>(src, dst);
    // K7: gather-accumulate (warp per node)
    {
        long long total = (long long)N_NODES * 32;
        int blocks = (int)((total + 255) / 256);
        gather_kernel<<<blocks, 256>>>(h, dnorm, out);
    }
}

// round 3
// speedup vs baseline: 1.1865x; 1.1057x over previous
#include <cuda_runtime.h>
#include <cuda_fp16.h>
#include <cuda_bf16.h>

#define N_NODES 100000
#define D_DIM   64
#define E_EDGES 1600000

#define SCAN_BLOCK 1024
#define N_SCAN_BLOCKS ((N_NODES + SCAN_BLOCK - 1) / SCAN_BLOCK)   // 98

// ---- device scratch (no cudaMalloc allowed) ----
__device__ float  g_adst[N_NODES];          // h[i].w_dst + bias
__device__ float2 g_spack[N_NODES];         // (h[i].w_src, dnorm[i])
__device__ int    g_counts[N_NODES];        // in-degree histogram
__device__ int    g_offsets[N_NODES + 1];   // CSR row offsets
__device__ int    g_cursor[N_NODES];        // scatter cursors
__device__ int    g_blocksums[N_SCAN_BLOCKS];
__device__ int    g_edge_src[E_EDGES];      // CSR column (src node) list
__device__ __half g_hhalf[N_NODES * D_DIM]; // fp16 mirror of h

// ---------------------------------------------------------------------------
// K1: per-node gate partials (warp per node) + fp16 mirror of h + zero counts
// ---------------------------------------------------------------------------
__global__ void node_dots_kernel(const float* __restrict__ h,
                                 const float* __restrict__ dnorm,
                                 const float* __restrict__ gate_w,
                                 const float* __restrict__ gate_b)
{
    int tid  = blockIdx.x * blockDim.x + threadIdx.x;
    int warp = tid >> 5;
    int lane = tid & 31;
    if (warp >= N_NODES) return;

    float2 hv = *reinterpret_cast<const float2*>(h + (long long)warp * D_DIM + lane * 2);

    // fp16 mirror (4B per lane = 128B per row)
    *reinterpret_cast<__half2*>(g_hhalf + (long long)warp * D_DIM + lane * 2) =
        __floats2half2_rn(hv.x, hv.y);

    float2 wd = *reinterpret_cast<const float2*>(gate_w + lane * 2);
    float2 ws = *reinterpret_cast<const float2*>(gate_w + D_DIM + lane * 2);

    float pd = hv.x * wd.x + hv.y * wd.y;
    float ps = hv.x * ws.x + hv.y * ws.y;

    #pragma unroll
    for (int off = 16; off > 0; off >>= 1) {
        pd += __shfl_xor_sync(0xFFFFFFFFu, pd, off);
        ps += __shfl_xor_sync(0xFFFFFFFFu, ps, off);
    }

    if (lane == 0) {
        g_adst[warp]   = pd + gate_b[0];
        g_spack[warp]  = make_float2(ps, dnorm[warp]);
        g_counts[warp] = 0;
    }
}

// ---------------------------------------------------------------------------
// K2: in-degree histogram
// ---------------------------------------------------------------------------
__global__ void histogram_kernel(const int* __restrict__ dst)
{
    int stride = gridDim.x * blockDim.x;
    for (int e = blockIdx.x * blockDim.x + threadIdx.x; e < E_EDGES; e += stride)
        atomicAdd(&g_counts[dst[e]], 1);
}

// ---------------------------------------------------------------------------
// K3: per-block exclusive scan (Hillis-Steele in smem), writes block sums
// ---------------------------------------------------------------------------
__global__ void scan_blocks_kernel()
{
    __shared__ int sdata[SCAN_BLOCK];
    int tid = threadIdx.x;
    int i   = blockIdx.x * SCAN_BLOCK + tid;
    int v   = (i < N_NODES) ? g_counts[i] : 0;
    sdata[tid] = v;
    __syncthreads();

    #pragma unroll
    for (int off = 1; off < SCAN_BLOCK; off <<= 1) {
        int t = (tid >= off) ? sdata[tid - off] : 0;
        __syncthreads();
        sdata[tid] += t;
        __syncthreads();
    }

    if (i < N_NODES) g_offsets[i] = sdata[tid] - v;       // exclusive, block-local
    if (tid == SCAN_BLOCK - 1) g_blocksums[blockIdx.x] = sdata[tid];
}

// ---------------------------------------------------------------------------
// K4: every block scans the 98 block sums in smem (redundant but trivial),
//     adds its base, inits cursors, fixes offsets[N].
//     Launch with SCAN_BLOCK threads, N_SCAN_BLOCKS blocks.
// ---------------------------------------------------------------------------
__global__ void add_base_kernel()
{
    __shared__ int ssum[128];
    int tid = threadIdx.x;
    if (tid < 128) {
        int v = (tid < N_SCAN_BLOCKS) ? g_blocksums[tid] : 0;
        ssum[tid] = v;
    }
    __syncthreads();
    if (tid < 128) {
        // serial-ish scan by thread 0 is fine for 98 values? no — do Hillis-Steele
    }
    // Hillis-Steele over 128 entries using first 128 threads
    #pragma unroll
    for (int off = 1; off < 128; off <<= 1) {
        int t = 0;
        if (tid < 128 && tid >= off) t = ssum[tid - off];
        __syncthreads();
        if (tid < 128) ssum[tid] += t;
        __syncthreads();
    }
    // exclusive base for this block
    int base = (blockIdx.x == 0) ? 0 : ssum[blockIdx.x - 1];

    int i = blockIdx.x * SCAN_BLOCK + tid;
    if (i < N_NODES) {
        int val = g_offsets[i] + base;
        g_offsets[i] = val;
        g_cursor[i]  = val;
    }
    if (blockIdx.x == 0 && tid == 0) g_offsets[N_NODES] = E_EDGES;
}

// ---------------------------------------------------------------------------
// K5: scatter src ids into CSR
// ---------------------------------------------------------------------------
__global__ void csr_scatter_kernel(const int* __restrict__ src,
                                   const int* __restrict__ dst)
{
    int stride = gridDim.x * blockDim.x;
    for (int e = blockIdx.x * blockDim.x + threadIdx.x; e < E_EDGES; e += stride) {
        int pos = atomicAdd(&g_cursor[dst[e]], 1);
        g_edge_src[pos] = src[e];
    }
}

// ---------------------------------------------------------------------------
// K6: gather-accumulate. One warp per dst node, fp16 h rows, no atomics.
// Per edge: one 8B gather (asrc,dnorm packed) + one 128B fp16 row.
// ---------------------------------------------------------------------------
__global__ void gather_kernel(const float* __restrict__ dnorm,
                              float* __restrict__ out)
{
    int tid  = blockIdx.x * blockDim.x + threadIdx.x;
    int d    = tid >> 5;
    int lane = tid & 31;
    if (d >= N_NODES) return;

    int beg = g_offsets[d];
    int end = g_offsets[d + 1];

    float adst_d = g_adst[d];
    float dnd    = dnorm[d];

    float accx = 0.f, accy = 0.f;

    const __half* __restrict__ hh = g_hhalf;

    for (int base = beg; base < end; base += 32) {
        int idx = base + lane;
        int s = 0;
        float coef = 0.f;
        if (idx < end) {
            s = g_edge_src[idx];
            float2 sp = g_spack[s];
            coef = tanhf(adst_d + sp.x) * dnd * sp.y;
        }
        int cnt = end - base;
        if (cnt > 32) cnt = 32;

        int j = 0;
        for (; j + 4 <= cnt; j += 4) {
            int   s0 = __shfl_sync(0xFFFFFFFFu, s, j);
            int   s1 = __shfl_sync(0xFFFFFFFFu, s, j + 1);
            int   s2 = __shfl_sync(0xFFFFFFFFu, s, j + 2);
            int   s3 = __shfl_sync(0xFFFFFFFFu, s, j + 3);
            float c0 = __shfl_sync(0xFFFFFFFFu, coef, j);
            float c1 = __shfl_sync(0xFFFFFFFFu, coef, j + 1);
            float c2 = __shfl_sync(0xFFFFFFFFu, coef, j + 2);
            float c3 = __shfl_sync(0xFFFFFFFFu, coef, j + 3);
            __half2 a0 = *reinterpret_cast<const __half2*>(hh + (long long)s0 * D_DIM + lane * 2);
            __half2 a1 = *reinterpret_cast<const __half2*>(hh + (long long)s1 * D_DIM + lane * 2);
            __half2 a2 = *reinterpret_cast<const __half2*>(hh + (long long)s2 * D_DIM + lane * 2);
            __half2 a3 = *reinterpret_cast<const __half2*>(hh + (long long)s3 * D_DIM + lane * 2);
            float2 f0 = __half22float2(a0);
            float2 f1 = __half22float2(a1);
            float2 f2 = __half22float2(a2);
            float2 f3 = __half22float2(a3);
            accx = fmaf(c0, f0.x, accx); accy = fmaf(c0, f0.y, accy);
            accx = fmaf(c1, f1.x, accx); accy = fmaf(c1, f1.y, accy);
            accx = fmaf(c2, f2.x, accx); accy = fmaf(c2, f2.y, accy);
            accx = fmaf(c3, f3.x, accx); accy = fmaf(c3, f3.y, accy);
        }
        for (; j < cnt; j++) {
            int   sj = __shfl_sync(0xFFFFFFFFu, s, j);
            float cj = __shfl_sync(0xFFFFFFFFu, coef, j);
            __half2 av = *reinterpret_cast<const __half2*>(hh + (long long)sj * D_DIM + lane * 2);
            float2 fv = __half22float2(av);
            accx = fmaf(cj, fv.x, accx);
            accy = fmaf(cj, fv.y, accy);
        }
    }

    *reinterpret_cast<float2*>(out + (long long)d * D_DIM + lane * 2) =
        make_float2(accx, accy);
}

// ---------------------------------------------------------------------------
// Launch
// ---------------------------------------------------------------------------
extern "C" void kernel_launch(void* const* d_in, const int* in_sizes, int n_in,
                              void* d_out, int out_size)
{
    const float* h      = (const float*)d_in[0];   // (N, 64)
    const float* dnorm  = (const float*)d_in[1];   // (N,)
    const float* gate_w = (const float*)d_in[2];   // (1, 128)
    const float* gate_b = (const float*)d_in[3];   // (1,)
    const int*   src    = (const int*)  d_in[4];   // (E,)
    const int*   dst    = (const int*)  d_in[5];   // (E,)
    float* out = (float*)d_out;                    // (N, 64) float32

    {
        long long total = (long long)N_NODES * 32;
        int blocks = (int)((total + 255) / 256);
        node_dots_kernel<<<blocks, 256>>>(h, dnorm, gate_w, gate_b);
    }
    histogram_kernel<<<2048, 256>>>(dst);
    scan_blocks_kernel<<<N_SCAN_BLOCKS, SCAN_BLOCK>>>();
    add_base_kernel<<<N_SCAN_BLOCKS, SCAN_BLOCK>>>();
    csr_scatter_kernel<<<2048, 256>>>(src, dst);
    {
        long long total = (long long)N_NODES * 32;
        int blocks = (int)((total + 255) / 256);
        gather_kernel<<<blocks, 256>>>(dnorm, out);
    }
}

// round 4
// speedup vs baseline: 1.3344x; 1.1247x over previous
#include <cuda_runtime.h>
#include <cuda_fp16.h>
#include <cuda_bf16.h>

#define N_NODES 100000
#define D_DIM   64
#define E_EDGES 1600000

#define SCAN_BLOCK 1024
#define N_SCAN_BLOCKS ((N_NODES + SCAN_BLOCK - 1) / SCAN_BLOCK)   // 98

// ---- device scratch (no cudaMalloc allowed; zero-initialized at load) ----
__device__ float  g_adst[N_NODES];          // h[i].w_dst + bias
__device__ float2 g_spack[N_NODES];         // (h[i].w_src, dnorm[i])
__device__ int    g_counts[N_NODES];        // in-degree histogram
                                            // INVARIANT: zero on kernel_launch entry
                                            // (re-zeroed by add_base_kernel each call)
__device__ int    g_offsets[N_NODES + 1];   // CSR row offsets
__device__ int    g_cursor[N_NODES];        // scatter cursors
__device__ int    g_blocksums[N_SCAN_BLOCKS];
__device__ int    g_edge_src[E_EDGES];      // CSR column (src node) list
__device__ __half g_hhalf[N_NODES * D_DIM]; // fp16 mirror of h

__device__ __forceinline__ float fast_tanh(float x) {
    float r;
    asm("tanh.approx.f32 %0, %1;" : "=f"(r) : "f"(x));
    return r;
}

// ---------------------------------------------------------------------------
// K1: per-node gate partials (warp per node) + fp16 mirror + FUSED histogram.
// Thread t also histograms edge t (3.2M threads >= 1.6M edges).
// Requires g_counts == 0 on entry (invariant restored by add_base_kernel).
// ---------------------------------------------------------------------------
__global__ void node_dots_hist_kernel(const float* __restrict__ h,
                                      const float* __restrict__ dnorm,
                                      const float* __restrict__ gate_w,
                                      const float* __restrict__ gate_b,
                                      const int*   __restrict__ dst)
{
    int tid  = blockIdx.x * blockDim.x + threadIdx.x;
    int warp = tid >> 5;
    int lane = tid & 31;

    if (tid < E_EDGES)
        atomicAdd(&g_counts[dst[tid]], 1);

    if (warp >= N_NODES) return;

    float2 hv = *reinterpret_cast<const float2*>(h + (long long)warp * D_DIM + lane * 2);

    // fp16 mirror (4B per lane = 128B per row)
    *reinterpret_cast<__half2*>(g_hhalf + (long long)warp * D_DIM + lane * 2) =
        __floats2half2_rn(hv.x, hv.y);

    float2 wd = *reinterpret_cast<const float2*>(gate_w + lane * 2);
    float2 ws = *reinterpret_cast<const float2*>(gate_w + D_DIM + lane * 2);

    float pd = hv.x * wd.x + hv.y * wd.y;
    float ps = hv.x * ws.x + hv.y * ws.y;

    #pragma unroll
    for (int off = 16; off > 0; off >>= 1) {
        pd += __shfl_xor_sync(0xFFFFFFFFu, pd, off);
        ps += __shfl_xor_sync(0xFFFFFFFFu, ps, off);
    }

    if (lane == 0) {
        g_adst[warp]  = pd + gate_b[0];
        g_spack[warp] = make_float2(ps, dnorm[warp]);
    }
}

// ---------------------------------------------------------------------------
// K2: per-block exclusive scan (Hillis-Steele in smem), writes block sums
// ---------------------------------------------------------------------------
__global__ void scan_blocks_kernel()
{
    __shared__ int sdata[SCAN_BLOCK];
    int tid = threadIdx.x;
    int i   = blockIdx.x * SCAN_BLOCK + tid;
    int v   = (i < N_NODES) ? g_counts[i] : 0;
    sdata[tid] = v;
    __syncthreads();

    #pragma unroll
    for (int off = 1; off < SCAN_BLOCK; off <<= 1) {
        int t = (tid >= off) ? sdata[tid - off] : 0;
        __syncthreads();
        sdata[tid] += t;
        __syncthreads();
    }

    if (i < N_NODES) g_offsets[i] = sdata[tid] - v;       // exclusive, block-local
    if (tid == SCAN_BLOCK - 1) g_blocksums[blockIdx.x] = sdata[tid];
}

// ---------------------------------------------------------------------------
// K3: every block scans the 98 block sums in smem, adds its base, inits
//     cursors, RE-ZEROES counts (restores K1's invariant), fixes offsets[N].
// ---------------------------------------------------------------------------
__global__ void add_base_kernel()
{
    __shared__ int ssum[128];
    int tid = threadIdx.x;
    if (tid < 128)
        ssum[tid] = (tid < N_SCAN_BLOCKS) ? g_blocksums[tid] : 0;
    __syncthreads();

    #pragma unroll
    for (int off = 1; off < 128; off <<= 1) {
        int t = 0;
        if (tid < 128 && tid >= off) t = ssum[tid - off];
        __syncthreads();
        if (tid < 128) ssum[tid] += t;
        __syncthreads();
    }
    int base = (blockIdx.x == 0) ? 0 : ssum[blockIdx.x - 1];

    int i = blockIdx.x * SCAN_BLOCK + tid;
    if (i < N_NODES) {
        int val = g_offsets[i] + base;
        g_offsets[i] = val;
        g_cursor[i]  = val;
        g_counts[i]  = 0;          // restore invariant for next replay
    }
    if (blockIdx.x == 0 && tid == 0) g_offsets[N_NODES] = E_EDGES;
}

// ---------------------------------------------------------------------------
// K4: scatter src ids into CSR
// ---------------------------------------------------------------------------
__global__ void csr_scatter_kernel(const int* __restrict__ src,
                                   const int* __restrict__ dst)
{
    int stride = gridDim.x * blockDim.x;
    for (int e = blockIdx.x * blockDim.x + threadIdx.x; e < E_EDGES; e += stride) {
        int pos = atomicAdd(&g_cursor[dst[e]], 1);
        g_edge_src[pos] = src[e];
    }
}

// ---------------------------------------------------------------------------
// K5: gather-accumulate. One warp per dst node, fp16 h rows, no atomics.
// Per edge: one 8B gather (asrc,dnorm packed) + one 128B fp16 row.
// ---------------------------------------------------------------------------
__global__ void gather_kernel(const float* __restrict__ dnorm,
                              float* __restrict__ out)
{
    int tid  = blockIdx.x * blockDim.x + threadIdx.x;
    int d    = tid >> 5;
    int lane = tid & 31;
    if (d >= N_NODES) return;

    int beg = g_offsets[d];
    int end = g_offsets[d + 1];

    float adst_d = g_adst[d];
    float dnd    = dnorm[d];

    float accx = 0.f, accy = 0.f;

    const __half* __restrict__ hh = g_hhalf;

    for (int base = beg; base < end; base += 32) {
        int idx = base + lane;
        int s = 0;
        float coef = 0.f;
        if (idx < end) {
            s = g_edge_src[idx];
            float2 sp = g_spack[s];
            coef = fast_tanh(adst_d + sp.x) * dnd * sp.y;
        }
        int cnt = end - base;
        if (cnt > 32) cnt = 32;

        int j = 0;
        for (; j + 4 <= cnt; j += 4) {
            int   s0 = __shfl_sync(0xFFFFFFFFu, s, j);
            int   s1 = __shfl_sync(0xFFFFFFFFu, s, j + 1);
            int   s2 = __shfl_sync(0xFFFFFFFFu, s, j + 2);
            int   s3 = __shfl_sync(0xFFFFFFFFu, s, j + 3);
            float c0 = __shfl_sync(0xFFFFFFFFu, coef, j);
            float c1 = __shfl_sync(0xFFFFFFFFu, coef, j + 1);
            float c2 = __shfl_sync(0xFFFFFFFFu, coef, j + 2);
            float c3 = __shfl_sync(0xFFFFFFFFu, coef, j + 3);
            __half2 a0 = *reinterpret_cast<const __half2*>(hh + (long long)s0 * D_DIM + lane * 2);
            __half2 a1 = *reinterpret_cast<const __half2*>(hh + (long long)s1 * D_DIM + lane * 2);
            __half2 a2 = *reinterpret_cast<const __half2*>(hh + (long long)s2 * D_DIM + lane * 2);
            __half2 a3 = *reinterpret_cast<const __half2*>(hh + (long long)s3 * D_DIM + lane * 2);
            float2 f0 = __half22float2(a0);
            float2 f1 = __half22float2(a1);
            float2 f2 = __half22float2(a2);
            float2 f3 = __half22float2(a3);
            accx = fmaf(c0, f0.x, accx); accy = fmaf(c0, f0.y, accy);
            accx = fmaf(c1, f1.x, accx); accy = fmaf(c1, f1.y, accy);
            accx = fmaf(c2, f2.x, accx); accy = fmaf(c2, f2.y, accy);
            accx = fmaf(c3, f3.x, accx); accy = fmaf(c3, f3.y, accy);
        }
        for (; j < cnt; j++) {
            int   sj = __shfl_sync(0xFFFFFFFFu, s, j);
            float cj = __shfl_sync(0xFFFFFFFFu, coef, j);
            __half2 av = *reinterpret_cast<const __half2*>(hh + (long long)sj * D_DIM + lane * 2);
            float2 fv = __half22float2(av);
            accx = fmaf(cj, fv.x, accx);
            accy = fmaf(cj, fv.y, accy);
        }
    }

    *reinterpret_cast<float2*>(out + (long long)d * D_DIM + lane * 2) =
        make_float2(accx, accy);
}

// ---------------------------------------------------------------------------
// Launch (5 kernels)
// ---------------------------------------------------------------------------
extern "C" void kernel_launch(void* const* d_in, const int* in_sizes, int n_in,
                              void* d_out, int out_size)
{
    const float* h      = (const float*)d_in[0];   // (N, 64)
    const float* dnorm  = (const float*)d_in[1];   // (N,)
    const float* gate_w = (const float*)d_in[2];   // (1, 128)
    const float* gate_b = (const float*)d_in[3];   // (1,)
    const int*   src    = (const int*)  d_in[4];   // (E,)
    const int*   dst    = (const int*)  d_in[5];   // (E,)
    float* out = (float*)d_out;                    // (N, 64) float32

    {
        long long total = (long long)N_NODES * 32;
        int blocks = (int)((total + 255) / 256);
        node_dots_hist_kernel<<<blocks, 256>>>(h, dnorm, gate_w, gate_b, dst);
    }
    scan_blocks_kernel<<<N_SCAN_BLOCKS, SCAN_BLOCK>>>();
    add_base_kernel<<<N_SCAN_BLOCKS, SCAN_BLOCK>>>();
    csr_scatter_kernel<<<2048, 256>>>(src, dst);
    {
        long long total = (long long)N_NODES * 32;
        int blocks = (int)((total + 255) / 256);
        gather_kernel<<<blocks, 256>>>(dnorm, out);
    }
}